// round 3
// baseline (speedup 1.0000x reference)
#include <cuda_runtime.h>
#include <cstdint>

#define EPS 1e-5f
typedef unsigned long long ull;

// ---------------- scratch (device globals; zero-init at load; halos never written) ----------
__device__ __align__(16) float  g_h1[2*34*34*34*32];   // conv1 out, +1 halo all sides, channel-last
__device__ __align__(16) float  g_h2[2*32*32*32*32];   // conv2 out, channel-last [b][z][y][x][ci]
__device__ unsigned char        g_m1[2*32*32*32];      // conv1 output-site mask
__device__ __align__(16) float  g_w1t[27*32];          // W1  -> [tap][co]
__device__ __align__(16) float2 g_w2t[27*16*32];       // W2  -> [tap][ci/2][co] (ci-pair packed)
__device__ __align__(16) float2 g_wvt[27*16*100];      // Winv-> [tap][ci/2][co]

__device__ __forceinline__ ull ffma2(ull a, ull b, ull c){
    ull d; asm("fma.rn.f32x2 %0, %1, %2, %3;" : "=l"(d) : "l"(a), "l"(b), "l"(c)); return d;
}
__device__ __forceinline__ float pair_sum(ull v){
    float lo = __uint_as_float((unsigned)(v & 0xffffffffu));
    float hi = __uint_as_float((unsigned)(v >> 32));
    return lo + hi;
}

// ---------------- k0: weight transposes -----------------------------------------------------
__global__ void k0_transpose(const float* __restrict__ W1, const float* __restrict__ W2,
                             const float* __restrict__ Wv)
{
    const int N1 = 27*32;            // g_w1t floats
    const int N2 = 27*16*32;         // g_w2t float2
    const int N3 = 27*16*100;        // g_wvt float2
    for (int i = blockIdx.x*blockDim.x + threadIdx.x; i < N1+N2+N3; i += gridDim.x*blockDim.x){
        if (i < N1){
            int tap = i >> 5, co = i & 31;
            g_w1t[i] = W1[co*27 + tap];
        } else if (i < N1+N2){
            int j = i - N1;
            int tap = j / 512, r = j % 512, cp = r >> 5, co = r & 31;
            g_w2t[j] = make_float2(W2[(co*32 + 2*cp    )*27 + tap],
                                   W2[(co*32 + 2*cp + 1)*27 + tap]);
        } else {
            int k = i - N1 - N2;
            int tap = k / 1600, r = k % 1600, cp = r / 100, co = r % 100;
            g_wvt[k] = make_float2(Wv[(co*32 + 2*cp    )*27 + tap],
                                   Wv[(co*32 + 2*cp + 1)*27 + tap]);
        }
    }
}

// ---------------- k1: conv1(s2) + BN + ReLU + mask  -> g_h1, g_m1 ----------------------------
// grid (32 y, 32 z, 2 b), 128 threads: lane=co, warp=xg (4 warps * 8 x each)
__global__ __launch_bounds__(128)
void k1_conv1(const float* __restrict__ x, const int* __restrict__ mask0,
              const float* __restrict__ b1, const float* __restrict__ g1,
              const float* __restrict__ bt1, const float* __restrict__ rm1,
              const float* __restrict__ rv1)
{
    __shared__ float sin_[9][65];
    __shared__ int   smk[9][65];
    __shared__ float sw[27*32];
    __shared__ float m1f[32];

    const int yy = blockIdx.x, zz = blockIdx.y, b = blockIdx.z;
    const int t = threadIdx.x, co = t & 31, xg = t >> 5;

    // stage 9 input rows + mask rows
    for (int i = t; i < 9*65; i += 128){
        int r = i / 65, xx = i % 65;
        int kz = r / 3, ky = r % 3;
        int iz = 2*zz + kz, iy = 2*yy + ky;
        long off = ((long)(b*65 + iz)*65 + iy)*65 + xx;
        sin_[r][xx] = x[off];
        smk[r][xx]  = mask0[off];
    }
    for (int i = t; i < 27*32; i += 128) sw[i] = g_w1t[i];
    __syncthreads();

    if (t < 32){
        int xo = t, m = 0;
        #pragma unroll
        for (int r = 0; r < 9; r++)
            m |= smk[r][2*xo] | smk[r][2*xo+1] | smk[r][2*xo+2];
        m1f[xo] = m ? 1.0f : 0.0f;
        g_m1[((b*32 + zz)*32 + yy)*32 + xo] = m ? 1 : 0;
    }
    __syncthreads();

    const float s  = g1[co] * rsqrtf(rv1[co] + EPS);
    const float bb = bt1[co] - rm1[co]*s;
    const float bc = b1[co];

    for (int i = 0; i < 8; i++){
        int xo = xg + 4*i;               // 4 warps x 8 iters = 32 x
        float acc = 0.f;
        #pragma unroll
        for (int r = 0; r < 9; r++){
            #pragma unroll
            for (int kx = 0; kx < 3; kx++)
                acc = fmaf(sin_[r][2*xo + kx], sw[(r*3 + kx)*32 + co], acc);
        }
        float h = fmaxf((acc + bc)*s + bb, 0.f) * m1f[xo];
        g_h1[(((long)(b*34 + zz+1)*34 + (yy+1))*34 + (xo+1))*32 + co] = h;
    }
}

// ---------------- k2: SubMConv 32->32 + BN + ReLU + mask -> g_h2 -----------------------------
// grid (32 y, 32 z, 2 b), 256 threads: lane=co, warp=xg (8 warps * 4 x each)
__global__ __launch_bounds__(256)
void k2_conv2(const float* __restrict__ b2, const float* __restrict__ g2,
              const float* __restrict__ bt2, const float* __restrict__ rm2,
              const float* __restrict__ rv2)
{
    __shared__ __align__(16) float sh[9*34*32];   // [kz*3+ky][xp 0..33][ci]  = 39168 B
    __shared__ float m1f[32];

    const int yy = blockIdx.x, zz = blockIdx.y, b = blockIdx.z;
    const int t = threadIdx.x, co = t & 31, w = t >> 5;
    const int x0 = w * 4;

    // stage 9 rows of padded h1 (each 34*32 floats, contiguous) via float4
    {
        float4* dst = reinterpret_cast<float4*>(sh);
        for (int i = t; i < 9*34*32/4; i += 256){
            int r = i / 272, rem = i % 272;
            int kz = r / 3, ky = r % 3;
            const float4* src = reinterpret_cast<const float4*>(
                g_h1 + (((long)(b*34 + zz+kz)*34 + (yy+ky))*34)*32);
            dst[r*272 + rem] = src[rem];
        }
        if (t < 32) m1f[t] = g_m1[((b*32 + zz)*32 + yy)*32 + t] ? 1.0f : 0.0f;
    }
    __syncthreads();

    const ull* shu = reinterpret_cast<const ull*>(sh);
    ull a0 = 0, a1 = 0, a2 = 0, a3 = 0;

    #pragma unroll 3
    for (int tap = 0; tap < 27; tap++){
        int kz = tap / 9, ky = (tap / 3) % 3, kx = tap % 3;
        const ull* h0 = shu + ((kz*3 + ky)*34 + (x0 + 0 + kx))*16;
        const ull* h1p = h0 + 16;
        const ull* h2p = h0 + 32;
        const ull* h3p = h0 + 48;
        const ull* wp = reinterpret_cast<const ull*>(g_w2t + tap*512) + co;
        #pragma unroll
        for (int cp = 0; cp < 16; cp++){
            ull wv = __ldg(wp + cp*32);
            a0 = ffma2(h0 [cp], wv, a0);
            a1 = ffma2(h1p[cp], wv, a1);
            a2 = ffma2(h2p[cp], wv, a2);
            a3 = ffma2(h3p[cp], wv, a3);
        }
    }

    const float s  = g2[co] * rsqrtf(rv2[co] + EPS);
    const float bb = bt2[co] - rm2[co]*s;
    const float bc = b2[co];
    float* out = g_h2 + (((long)(b*32 + zz)*32 + yy)*32)*32;
    float v0 = fmaxf((pair_sum(a0) + bc)*s + bb, 0.f) * m1f[x0+0];
    float v1 = fmaxf((pair_sum(a1) + bc)*s + bb, 0.f) * m1f[x0+1];
    float v2 = fmaxf((pair_sum(a2) + bc)*s + bb, 0.f) * m1f[x0+2];
    float v3 = fmaxf((pair_sum(a3) + bc)*s + bb, 0.f) * m1f[x0+3];
    out[(x0+0)*32 + co] = v0;
    out[(x0+1)*32 + co] = v1;
    out[(x0+2)*32 + co] = v2;
    out[(x0+3)*32 + co] = v3;
}

// ---------------- k3: inverse conv 32->100 masked by mask0 -> d_out --------------------------
// grid (65 y, 65 z, 2 b), 128 threads. thread t<100 owns co=t during compute.
__global__ __launch_bounds__(128)
void k3_inv(const int* __restrict__ mask0, const float* __restrict__ binv,
            float* __restrict__ out)
{
    __shared__ __align__(16) float sh[4*34*32];   // [zi*2+yi][px 0..33][ci] = 17408 B
    __shared__ int   mrow[65];
    __shared__ int   zq[2], zk[2], yq[2], yk[2], nZY[2];

    const int yy = blockIdx.x, zz = blockIdx.y, b = blockIdx.z;
    const int t = threadIdx.x;
    const long plane = (long)65*65*65;
    const long site  = ((long)zz*65 + yy)*65;

    if (t < 65) mrow[t] = mask0[(long)b*plane + site + t];
    if (t == 0){
        if (zz & 1){ nZY[0]=1; zq[0]=(zz-1)>>1; zk[0]=1; zq[1]=-1; zk[1]=0; }
        else       { nZY[0]=2; zq[0]=(zz>>1)-1; zk[0]=0; zq[1]=zz>>1; zk[1]=2; }
        if (yy & 1){ nZY[1]=1; yq[0]=(yy-1)>>1; yk[0]=1; yq[1]=-1; yk[1]=0; }
        else       { nZY[1]=2; yq[0]=(yy>>1)-1; yk[0]=0; yq[1]=yy>>1; yk[1]=2; }
    }
    __syncthreads();

    // zero-fill the whole (b, :, z, y, :) row block, coalesced
    for (int i = t; i < 100*65; i += 128){
        int co = i / 65, xx = i % 65;
        out[((long)(b*100 + co))*plane + site + xx] = 0.f;
    }

    // stage candidate h2 rows into padded smem (zeros at px=0 and px=33, zeros if q out of range)
    const int nZ = nZY[0], nY = nZY[1];
    for (int zi = 0; zi < 2; zi++){
        for (int yi = 0; yi < 2; yi++){
            if (zi >= nZ || yi >= nY) continue;
            int q0 = zq[zi], q1 = yq[yi];
            bool valid = (q0 >= 0 && q0 < 32 && q1 >= 0 && q1 < 32);
            float4* dst = reinterpret_cast<float4*>(sh + (zi*2 + yi)*34*32);
            const float4* src = valid ? reinterpret_cast<const float4*>(
                g_h2 + (((long)(b*32 + q0)*32 + q1)*32)*32) : nullptr;
            for (int f = t; f < 272; f += 128){
                int px = f >> 3, c4 = f & 7;
                float4 v = make_float4(0.f,0.f,0.f,0.f);
                if (valid && px >= 1 && px <= 32) v = src[(px-1)*8 + c4];
                dst[px*8 + c4] = v;
            }
        }
    }
    __syncthreads();

    if (t >= 100) return;
    const int co = t;
    const ull* shu = reinterpret_cast<const ull*>(sh);
    const ull* wvt = reinterpret_cast<const ull*>(g_wvt);
    const float bc = binv[co];
    float* orow = out + ((long)(b*100 + co))*plane + site;

    for (int xx = 0; xx < 65; xx++){
        if (!mrow[xx]) continue;
        ull acc = 0;
        const bool odd = xx & 1;
        const int pxA = odd ? ((xx+1) >> 1) : (xx >> 1);       // kx=1  or kx=0
        const int pxB = (xx >> 1) + 1;                          // kx=2 (even only)
        for (int zi = 0; zi < nZ; zi++){
            const int kz = zk[zi];
            for (int yi = 0; yi < nY; yi++){
                const int ky = yk[yi];
                const int tapb = (kz*3 + ky)*3;
                const ull* hrow = shu + (zi*2 + yi)*34*16;
                if (odd){
                    const ull* hp = hrow + pxA*16;
                    const ull* wp = wvt + (tapb + 1)*16*100 + co;
                    #pragma unroll
                    for (int cp = 0; cp < 16; cp++)
                        acc = ffma2(hp[cp], __ldg(wp + cp*100), acc);
                } else {
                    const ull* hpA = hrow + pxA*16;
                    const ull* hpB = hrow + pxB*16;
                    const ull* wpA = wvt + (tapb + 0)*16*100 + co;
                    const ull* wpB = wvt + (tapb + 2)*16*100 + co;
                    #pragma unroll
                    for (int cp = 0; cp < 16; cp++){
                        acc = ffma2(hpA[cp], __ldg(wpA + cp*100), acc);
                        acc = ffma2(hpB[cp], __ldg(wpB + cp*100), acc);
                    }
                }
            }
        }
        orow[xx] = pair_sum(acc) + bc;
    }
}

// ---------------- launch ---------------------------------------------------------------------
extern "C" void kernel_launch(void* const* d_in, const int* in_sizes, int n_in,
                              void* d_out, int out_size)
{
    const float* x     = (const float*)d_in[0];
    const int*   mask0 = (const int*)  d_in[1];
    const float* W1    = (const float*)d_in[2];
    const float* b1    = (const float*)d_in[3];
    const float* g1    = (const float*)d_in[4];
    const float* bt1   = (const float*)d_in[5];
    const float* rm1   = (const float*)d_in[6];
    const float* rv1   = (const float*)d_in[7];
    const float* W2    = (const float*)d_in[8];
    const float* b2    = (const float*)d_in[9];
    const float* g2    = (const float*)d_in[10];
    const float* bt2   = (const float*)d_in[11];
    const float* rm2   = (const float*)d_in[12];
    const float* rv2   = (const float*)d_in[13];
    const float* Winv  = (const float*)d_in[14];
    const float* binv  = (const float*)d_in[15];
    float* out = (float*)d_out;

    k0_transpose<<<64, 256>>>(W1, W2, Winv);
    k1_conv1<<<dim3(32,32,2), 128>>>(x, mask0, b1, g1, bt1, rm1, rv1);
    k2_conv2<<<dim3(32,32,2), 256>>>(b2, g2, bt2, rm2, rv2);
    k3_inv  <<<dim3(65,65,2), 128>>>(mask0, binv, out);
}